// round 4
// baseline (speedup 1.0000x reference)
#include <cuda_runtime.h>
#include <math.h>

// ---------------- problem constants ----------------
#define B_SZ   16
#define H_SZ   56
#define W_SZ   56
#define C_DIM  512
#define WS     7
#define NH     16
#define HD     32
#define HID    2048
#define NTOK   49          // WS*WS
#define NWIN   64          // (H/WS)*(W/WS)
#define M_TOK  50176       // B * H * W
#define SCALE_F 0.17677669529663687f

// ---------------- scratch (device globals; no allocation) ----------------
__device__ float g_h[25690112];     // LN output (reused for LN2)
__device__ float g_q[25690112];     // (1024,16,49,32)
__device__ float g_k[25690112];
__device__ float g_v[25690112];
__device__ float g_attn[25690112];  // attention out in (B,L,C) token layout
__device__ float g_act[102760448];  // FC1 output (50176 x 2048)

// ---------------- LayerNorm: one row (512) per 128-thread block ----------
__global__ void __launch_bounds__(128) ln_kernel(
    const float* __restrict__ x, const float* __restrict__ gw,
    const float* __restrict__ bw, float* __restrict__ out)
{
    __shared__ float red[8];
    int row = blockIdx.x;
    int tid = threadIdx.x;
    const float4* xr = reinterpret_cast<const float4*>(x + (size_t)row * C_DIM);
    float4 v = xr[tid];
    float s  = v.x + v.y + v.z + v.w;
    float ss = v.x*v.x + v.y*v.y + v.z*v.z + v.w*v.w;
    #pragma unroll
    for (int o = 16; o > 0; o >>= 1) {
        s  += __shfl_xor_sync(0xFFFFFFFFu, s,  o);
        ss += __shfl_xor_sync(0xFFFFFFFFu, ss, o);
    }
    int warp = tid >> 5;
    if ((tid & 31) == 0) { red[warp] = s; red[4 + warp] = ss; }
    __syncthreads();
    float st  = red[0] + red[1] + red[2] + red[3];
    float sst = red[4] + red[5] + red[6] + red[7];
    float mu  = st * (1.0f / C_DIM);
    float var = sst * (1.0f / C_DIM) - mu * mu;
    float inv = rsqrtf(var + 1e-5f);
    float4 gv = reinterpret_cast<const float4*>(gw)[tid];
    float4 bv = reinterpret_cast<const float4*>(bw)[tid];
    float4 o;
    o.x = (v.x - mu) * inv * gv.x + bv.x;
    o.y = (v.y - mu) * inv * gv.y + bv.y;
    o.z = (v.z - mu) * inv * gv.z + bv.z;
    o.w = (v.w - mu) * inv * gv.w + bv.w;
    reinterpret_cast<float4*>(out + (size_t)row * C_DIM)[tid] = o;
}

// ---------------- SGEMM 128x128x16, 256 thr, 8x8/thread ------------------
#define BM 128
#define BN 128
#define BK 16
#define TM 8
#define TN 8

#define MODE_QKV  0
#define MODE_PROJ 1
#define MODE_FC1  2
#define MODE_FC2  3

template<int MODE>
__global__ void __launch_bounds__(256) gemm_kernel(
    const float* __restrict__ A,     // M x K
    const float* __restrict__ W,     // K x Ncols
    const float* __restrict__ bias,  // Ncols
    const float* __restrict__ resid, // M x Ncols (PROJ/FC2) or null
    float* __restrict__ out,
    int K, int Ncols)
{
    __shared__ float As[BK][BM];
    __shared__ float Bs[BK][BN];
    int tid = threadIdx.x;
    int m0 = blockIdx.y * BM;
    int n0 = blockIdx.x * BN;
    int tm = (tid >> 4) * TM;
    int tn = (tid & 15) * TN;
    float acc[TM][TN];
    #pragma unroll
    for (int i = 0; i < TM; i++)
        #pragma unroll
        for (int j = 0; j < TN; j++) acc[i][j] = 0.0f;

    const float* Aptr = A + (size_t)m0 * K;
    const float* Wptr = W + n0;

    for (int k0 = 0; k0 < K; k0 += BK) {
        // A tile: 128x16 -> As transposed [k][m]
        #pragma unroll
        for (int i = 0; i < 2; i++) {
            int slot = tid * 2 + i;           // 0..511
            int r  = slot >> 2;               // row 0..127
            int cv = (slot & 3) * 4;          // k offset
            float4 av = *reinterpret_cast<const float4*>(Aptr + (size_t)r * K + k0 + cv);
            As[cv + 0][r] = av.x;
            As[cv + 1][r] = av.y;
            As[cv + 2][r] = av.z;
            As[cv + 3][r] = av.w;
        }
        // B tile: 16x128
        #pragma unroll
        for (int i = 0; i < 2; i++) {
            int slot = tid * 2 + i;           // 0..511
            int r  = slot >> 5;               // 0..15
            int cv = (slot & 31) * 4;
            float4 bv = *reinterpret_cast<const float4*>(Wptr + (size_t)(k0 + r) * Ncols + cv);
            *reinterpret_cast<float4*>(&Bs[r][cv]) = bv;
        }
        __syncthreads();
        #pragma unroll
        for (int kk = 0; kk < BK; kk++) {
            float a[TM], b[TN];
            #pragma unroll
            for (int i = 0; i < TM; i++) a[i] = As[kk][tm + i];
            #pragma unroll
            for (int j = 0; j < TN; j++) b[j] = Bs[kk][tn + j];
            #pragma unroll
            for (int i = 0; i < TM; i++)
                #pragma unroll
                for (int j = 0; j < TN; j++)
                    acc[i][j] = fmaf(a[i], b[j], acc[i][j]);
        }
        __syncthreads();
    }

    // ---------------- epilogues ----------------
    if (MODE == MODE_QKV) {
        // scatter into windowed layout (g, head, n, d)
        #pragma unroll
        for (int i = 0; i < TM; i++) {
            int t  = m0 + tm + i;
            int bb = t / 3136;
            int l  = t - bb * 3136;
            int hr = l / 56;
            int wc = l - hr * 56;
            int gwin = bb * NWIN + (hr / WS) * 8 + (wc / WS);
            int n  = (hr % WS) * WS + (wc % WS);
            size_t ob = (size_t)gwin * (NH * NTOK * HD) + (size_t)n * HD;
            #pragma unroll
            for (int j = 0; j < TN; j++) {
                int col = n0 + tn + j;
                int head = col >> 5, d = col & 31;
                out[ob + (size_t)head * (NTOK * HD) + d] = acc[i][j] + bias[col];
            }
        }
    } else if (MODE == MODE_PROJ) {
        #pragma unroll
        for (int i = 0; i < TM; i++) {
            size_t ro = (size_t)(m0 + tm + i) * Ncols;
            #pragma unroll
            for (int j = 0; j < TN; j++) {
                int col = n0 + tn + j;
                out[ro + col] = acc[i][j] + bias[col] + resid[ro + col];
            }
        }
    } else if (MODE == MODE_FC1) {
        #pragma unroll
        for (int i = 0; i < TM; i++) {
            size_t ro = (size_t)(m0 + tm + i) * Ncols;
            #pragma unroll
            for (int j = 0; j < TN; j++) {
                int col = n0 + tn + j;
                float vv = acc[i][j] + bias[col];
                out[ro + col] = 0.5f * vv * (1.0f + erff(vv * 0.70710678118654752f));
            }
        }
    } else { // MODE_FC2: out = resid(=out) + W@A + bias
        #pragma unroll
        for (int i = 0; i < TM; i++) {
            size_t ro = (size_t)(m0 + tm + i) * Ncols;
            #pragma unroll
            for (int j = 0; j < TN; j++) {
                int col = n0 + tn + j;
                out[ro + col] = resid[ro + col] + acc[i][j] + bias[col];
            }
        }
    }
}

// ---------------- attention: one block per (head, window) ----------------
__global__ void __launch_bounds__(128) attn_kernel(
    const float* __restrict__ q, const float* __restrict__ k,
    const float* __restrict__ v, const float* __restrict__ rb,
    float* __restrict__ out)
{
    __shared__ float qs[NTOK * 33];
    __shared__ float ks[NTOK * 33];
    __shared__ float vs[NTOK * 33];
    __shared__ float S[NTOK * NTOK];

    int head = blockIdx.x;
    int g    = blockIdx.y;
    int tid  = threadIdx.x;
    size_t base = ((size_t)g * NH + head) * (NTOK * HD);

    for (int i = tid; i < NTOK * HD; i += 128) {
        int n = i >> 5, d = i & 31;
        qs[n * 33 + d] = q[base + i];
        ks[n * 33 + d] = k[base + i];
        vs[n * 33 + d] = v[base + i];
    }
    __syncthreads();

    const float* rbh = rb + (size_t)head * NTOK * NTOK;
    for (int idx = tid; idx < NTOK * NTOK; idx += 128) {
        int n = idx / NTOK, m = idx - n * NTOK;
        float acc = 0.0f;
        #pragma unroll
        for (int d = 0; d < HD; d++)
            acc = fmaf(qs[n * 33 + d], ks[m * 33 + d], acc);
        S[idx] = acc * SCALE_F + rbh[idx];
    }
    __syncthreads();

    if (tid < NTOK) {
        float mx = -1e30f;
        #pragma unroll 7
        for (int m = 0; m < NTOK; m++) mx = fmaxf(mx, S[tid * NTOK + m]);
        float sum = 0.0f;
        #pragma unroll 7
        for (int m = 0; m < NTOK; m++) {
            float e = __expf(S[tid * NTOK + m] - mx);
            S[tid * NTOK + m] = e;
            sum += e;
        }
        float r = 1.0f / sum;
        #pragma unroll 7
        for (int m = 0; m < NTOK; m++) S[tid * NTOK + m] *= r;
    }
    __syncthreads();

    int bb = g >> 6;
    int wi = g & 63;
    int hr0 = (wi >> 3) * WS, wc0 = (wi & 7) * WS;
    for (int idx = tid; idx < NTOK * HD; idx += 128) {
        int n = idx >> 5, d = idx & 31;
        float acc = 0.0f;
        #pragma unroll 7
        for (int m = 0; m < NTOK; m++)
            acc = fmaf(S[n * NTOK + m], vs[m * 33 + d], acc);
        int hr = hr0 + n / WS, wc = wc0 + n % WS;
        size_t t = (size_t)bb * 3136 + (size_t)hr * 56 + wc;
        out[t * C_DIM + head * HD + d] = acc;
    }
}

// ---------------- launch ----------------
extern "C" void kernel_launch(void* const* d_in, const int* in_sizes, int n_in,
                              void* d_out, int out_size)
{
    const float* x    = (const float*)d_in[0];
    const float* Wq   = (const float*)d_in[1];
    const float* bq   = (const float*)d_in[2];
    const float* Wk   = (const float*)d_in[3];
    const float* bk   = (const float*)d_in[4];
    const float* Wv   = (const float*)d_in[5];
    const float* bv   = (const float*)d_in[6];
    const float* Wp   = (const float*)d_in[7];
    const float* bp   = (const float*)d_in[8];
    const float* rbias= (const float*)d_in[9];
    const float* g1   = (const float*)d_in[10];
    const float* b1   = (const float*)d_in[11];
    const float* g2   = (const float*)d_in[12];
    const float* b2   = (const float*)d_in[13];
    const float* W1   = (const float*)d_in[14];
    const float* bfc1 = (const float*)d_in[15];
    const float* W2   = (const float*)d_in[16];
    const float* bfc2 = (const float*)d_in[17];
    float* out = (float*)d_out;

    float *h, *q, *k, *v, *attn, *act;
    cudaGetSymbolAddress((void**)&h,    g_h);
    cudaGetSymbolAddress((void**)&q,    g_q);
    cudaGetSymbolAddress((void**)&k,    g_k);
    cudaGetSymbolAddress((void**)&v,    g_v);
    cudaGetSymbolAddress((void**)&attn, g_attn);
    cudaGetSymbolAddress((void**)&act,  g_act);

    dim3 gemm512(4, M_TOK / BM);    // N=512
    dim3 gemm2048(16, M_TOK / BM);  // N=2048
    dim3 attn_grid(NH, B_SZ * NWIN);

    // 1) LN1
    ln_kernel<<<M_TOK, 128>>>(x, g1, b1, h);
    // 2) QKV projections with fused window-partition scatter
    gemm_kernel<MODE_QKV><<<gemm512, 256>>>(h, Wq, bq, nullptr, q, C_DIM, C_DIM);
    gemm_kernel<MODE_QKV><<<gemm512, 256>>>(h, Wk, bk, nullptr, k, C_DIM, C_DIM);
    gemm_kernel<MODE_QKV><<<gemm512, 256>>>(h, Wv, bv, nullptr, v, C_DIM, C_DIM);
    // 3) windowed attention with fused window-reverse
    attn_kernel<<<attn_grid, 128>>>(q, k, v, rbias, attn);
    // 4) proj + residual -> out (x1)
    gemm_kernel<MODE_PROJ><<<gemm512, 256>>>(attn, Wp, bp, x, out, C_DIM, C_DIM);
    // 5) LN2
    ln_kernel<<<M_TOK, 128>>>(out, g2, b2, h);
    // 6) FC1 + exact GELU
    gemm_kernel<MODE_FC1><<<gemm2048, 256>>>(h, W1, bfc1, nullptr, act, C_DIM, HID);
    // 7) FC2 + bias + residual -> out
    gemm_kernel<MODE_FC2><<<gemm512, 256>>>(act, W2, bfc2, out, out, HID, C_DIM);
}

// round 8
// speedup vs baseline: 1.9755x; 1.9755x over previous
#include <cuda_runtime.h>
#include <math.h>

// ---------------- problem constants ----------------
#define B_SZ   16
#define C_DIM  512
#define WS     7
#define NH     16
#define HD     32
#define HID    2048
#define NTOK   49
#define NWIN   64
#define M_TOK  50176
#define SCALE_F 0.17677669529663687f

// ---------------- scratch (device globals; no allocation) ----------------
__device__ float g_h[25690112];
__device__ float g_q[25690112];
__device__ float g_k[25690112];
__device__ float g_v[25690112];
__device__ float g_attn[25690112];
__device__ float g_act[102760448];

// ---------------- LayerNorm ----------
__global__ void __launch_bounds__(128) ln_kernel(
    const float* __restrict__ x, const float* __restrict__ gw,
    const float* __restrict__ bw, float* __restrict__ out)
{
    __shared__ float red[8];
    int row = blockIdx.x;
    int tid = threadIdx.x;
    const float4* xr = reinterpret_cast<const float4*>(x + (size_t)row * C_DIM);
    float4 v = xr[tid];
    float s  = v.x + v.y + v.z + v.w;
    float ss = v.x*v.x + v.y*v.y + v.z*v.z + v.w*v.w;
    #pragma unroll
    for (int o = 16; o > 0; o >>= 1) {
        s  += __shfl_xor_sync(0xFFFFFFFFu, s,  o);
        ss += __shfl_xor_sync(0xFFFFFFFFu, ss, o);
    }
    int warp = tid >> 5;
    if ((tid & 31) == 0) { red[warp] = s; red[4 + warp] = ss; }
    __syncthreads();
    float st  = red[0] + red[1] + red[2] + red[3];
    float sst = red[4] + red[5] + red[6] + red[7];
    float mu  = st * (1.0f / C_DIM);
    float var = sst * (1.0f / C_DIM) - mu * mu;
    float inv = rsqrtf(var + 1e-5f);
    float4 gv = reinterpret_cast<const float4*>(gw)[tid];
    float4 bv = reinterpret_cast<const float4*>(bw)[tid];
    float4 o;
    o.x = (v.x - mu) * inv * gv.x + bv.x;
    o.y = (v.y - mu) * inv * gv.y + bv.y;
    o.z = (v.z - mu) * inv * gv.z + bv.z;
    o.w = (v.w - mu) * inv * gv.w + bv.w;
    reinterpret_cast<float4*>(out + (size_t)row * C_DIM)[tid] = o;
}

// ---------------- tf32 tensor-core GEMM 128x128, BK=16 ----------------
#define BM 128
#define BN 128
#define BKT 16
#define PAD 4
#define LDA (BM + PAD)
#define LDB (BN + PAD)

#define MODE_QKV  0
#define MODE_PROJ 1
#define MODE_FC1  2
#define MODE_FC2  3

__device__ __forceinline__ float f2tf32(float f) {
    unsigned r;
    asm("cvt.rna.tf32.f32 %0, %1;" : "=r"(r) : "f"(f));
    return __uint_as_float(r);
}

__device__ __forceinline__ void mma_tf32(
    float& c0, float& c1, float& c2, float& c3,
    unsigned a0, unsigned a1, unsigned a2, unsigned a3,
    unsigned b0, unsigned b1)
{
    asm volatile(
        "mma.sync.aligned.m16n8k8.row.col.f32.tf32.tf32.f32 "
        "{%0,%1,%2,%3}, {%4,%5,%6,%7}, {%8,%9}, {%0,%1,%2,%3};"
        : "+f"(c0), "+f"(c1), "+f"(c2), "+f"(c3)
        : "r"(a0), "r"(a1), "r"(a2), "r"(a3), "r"(b0), "r"(b1));
}

template<int MODE>
__global__ void __launch_bounds__(256) tgemm_kernel(
    const float* __restrict__ A,     // M x K
    const float* __restrict__ W,     // K x Ncols
    const float* __restrict__ bias,
    const float* __restrict__ resid,
    float* __restrict__ out,
    int K, int Ncols)
{
    __shared__ float As[2][BKT][LDA];   // [k][m]
    __shared__ float Bs[2][BKT][LDB];   // [k][n]

    int tid  = threadIdx.x;
    int lane = tid & 31;
    int warp = tid >> 5;
    int gq   = lane >> 2;     // group 0..7
    int tig  = lane & 3;      // 0..3
    int wm   = warp >> 2;     // 0..1  (64 rows each)
    int wn   = warp & 3;      // 0..3  (32 cols each)
    int m0 = blockIdx.y * BM;
    int n0 = blockIdx.x * BN;

    float acc[4][4][4];       // [mtile][ntile][c0..c3]
    #pragma unroll
    for (int i = 0; i < 4; i++)
        #pragma unroll
        for (int j = 0; j < 4; j++)
            #pragma unroll
            for (int c = 0; c < 4; c++) acc[i][j][c] = 0.0f;

    const float* Aptr = A + (size_t)m0 * K;
    const float* Wptr = W + n0;

    // load slots: A -> 2 float4 per thread (128 rows x 4 f4/row)
    //             B -> 2 float4 per thread (16 rows x 32 f4/row)
    int slot0 = tid * 2;
    int ar0 = slot0 >> 2,        ac0 = (slot0 & 3) * 4;
    int ar1 = (slot0+1) >> 2,    ac1 = ((slot0+1) & 3) * 4;
    int br0 = slot0 >> 5,        bc0 = (slot0 & 31) * 4;
    int br1 = (slot0+1) >> 5,    bc1 = ((slot0+1) & 31) * 4;

    float4 pa0, pa1, pb0, pb1;

    auto fetch = [&](int k0) {
        pa0 = *reinterpret_cast<const float4*>(Aptr + (size_t)ar0 * K + k0 + ac0);
        pa1 = *reinterpret_cast<const float4*>(Aptr + (size_t)ar1 * K + k0 + ac1);
        pb0 = *reinterpret_cast<const float4*>(Wptr + (size_t)(k0 + br0) * Ncols + bc0);
        pb1 = *reinterpret_cast<const float4*>(Wptr + (size_t)(k0 + br1) * Ncols + bc1);
    };
    auto stage = [&](int buf) {
        As[buf][ac0 + 0][ar0] = f2tf32(pa0.x);
        As[buf][ac0 + 1][ar0] = f2tf32(pa0.y);
        As[buf][ac0 + 2][ar0] = f2tf32(pa0.z);
        As[buf][ac0 + 3][ar0] = f2tf32(pa0.w);
        As[buf][ac1 + 0][ar1] = f2tf32(pa1.x);
        As[buf][ac1 + 1][ar1] = f2tf32(pa1.y);
        As[buf][ac1 + 2][ar1] = f2tf32(pa1.z);
        As[buf][ac1 + 3][ar1] = f2tf32(pa1.w);
        float4 t0 = make_float4(f2tf32(pb0.x), f2tf32(pb0.y), f2tf32(pb0.z), f2tf32(pb0.w));
        float4 t1 = make_float4(f2tf32(pb1.x), f2tf32(pb1.y), f2tf32(pb1.z), f2tf32(pb1.w));
        *reinterpret_cast<float4*>(&Bs[buf][br0][bc0]) = t0;
        *reinterpret_cast<float4*>(&Bs[buf][br1][bc1]) = t1;
    };
    auto compute = [&](int buf) {
        #pragma unroll
        for (int ks = 0; ks < BKT; ks += 8) {
            unsigned afr[4][4];
            #pragma unroll
            for (int mt = 0; mt < 4; mt++) {
                int mrow = wm * 64 + mt * 16;
                afr[mt][0] = __float_as_uint(As[buf][ks + tig    ][mrow + gq    ]);
                afr[mt][1] = __float_as_uint(As[buf][ks + tig    ][mrow + gq + 8]);
                afr[mt][2] = __float_as_uint(As[buf][ks + tig + 4][mrow + gq    ]);
                afr[mt][3] = __float_as_uint(As[buf][ks + tig + 4][mrow + gq + 8]);
            }
            unsigned bfr[4][2];
            #pragma unroll
            for (int nt = 0; nt < 4; nt++) {
                int ncol = wn * 32 + nt * 8 + gq;
                bfr[nt][0] = __float_as_uint(Bs[buf][ks + tig    ][ncol]);
                bfr[nt][1] = __float_as_uint(Bs[buf][ks + tig + 4][ncol]);
            }
            #pragma unroll
            for (int mt = 0; mt < 4; mt++)
                #pragma unroll
                for (int nt = 0; nt < 4; nt++)
                    mma_tf32(acc[mt][nt][0], acc[mt][nt][1], acc[mt][nt][2], acc[mt][nt][3],
                             afr[mt][0], afr[mt][1], afr[mt][2], afr[mt][3],
                             bfr[nt][0], bfr[nt][1]);
        }
    };

    fetch(0);
    stage(0);
    __syncthreads();
    int buf = 0;
    for (int k0 = BKT; k0 <= K; k0 += BKT) {
        bool has = (k0 < K);
        if (has) fetch(k0);
        compute(buf);
        if (has) {
            stage(buf ^ 1);
            __syncthreads();
            buf ^= 1;
        }
    }

    // ---------------- epilogues ----------------
    #pragma unroll
    for (int mt = 0; mt < 4; mt++) {
        #pragma unroll
        for (int hh = 0; hh < 2; hh++) {
            int row = m0 + wm * 64 + mt * 16 + gq + hh * 8;
            if (MODE == MODE_QKV) {
                int bb = row / 3136;
                int l  = row - bb * 3136;
                int hr = l / 56;
                int wc = l - hr * 56;
                int gwin = bb * NWIN + (hr / WS) * 8 + (wc / WS);
                int n  = (hr % WS) * WS + (wc % WS);
                size_t ob = (size_t)gwin * (NH * NTOK * HD) + (size_t)n * HD;
                #pragma unroll
                for (int nt = 0; nt < 4; nt++) {
                    int col = n0 + wn * 32 + nt * 8 + 2 * tig;
                    float v0 = acc[mt][nt][2 * hh];
                    float v1 = acc[mt][nt][2 * hh + 1];
                    int head = col >> 5, d = col & 31;
                    out[ob + (size_t)head * (NTOK * HD) + d]     = v0 + bias[col];
                    out[ob + (size_t)head * (NTOK * HD) + d + 1] = v1 + bias[col + 1];
                }
            } else {
                size_t ro = (size_t)row * Ncols;
                #pragma unroll
                for (int nt = 0; nt < 4; nt++) {
                    int col = n0 + wn * 32 + nt * 8 + 2 * tig;
                    float v0 = acc[mt][nt][2 * hh];
                    float v1 = acc[mt][nt][2 * hh + 1];
                    if (MODE == MODE_PROJ) {
                        out[ro + col]     = v0 + bias[col]     + resid[ro + col];
                        out[ro + col + 1] = v1 + bias[col + 1] + resid[ro + col + 1];
                    } else if (MODE == MODE_FC1) {
                        float a0 = v0 + bias[col];
                        float a1 = v1 + bias[col + 1];
                        out[ro + col]     = 0.5f * a0 * (1.0f + erff(a0 * 0.70710678118654752f));
                        out[ro + col + 1] = 0.5f * a1 * (1.0f + erff(a1 * 0.70710678118654752f));
                    } else { // FC2
                        out[ro + col]     = resid[ro + col]     + v0 + bias[col];
                        out[ro + col + 1] = resid[ro + col + 1] + v1 + bias[col + 1];
                    }
                }
            }
        }
    }
}

// ---------------- attention: one block per (head, window) ----------------
__global__ void __launch_bounds__(128) attn_kernel(
    const float* __restrict__ q, const float* __restrict__ k,
    const float* __restrict__ v, const float* __restrict__ rb,
    float* __restrict__ out)
{
    __shared__ float qs[NTOK * 33];
    __shared__ float ks[NTOK * 33];
    __shared__ float vs[NTOK * 33];
    __shared__ float S[NTOK * NTOK];

    int head = blockIdx.x;
    int g    = blockIdx.y;
    int tid  = threadIdx.x;
    size_t base = ((size_t)g * NH + head) * (NTOK * HD);

    for (int i = tid; i < NTOK * HD; i += 128) {
        int n = i >> 5, d = i & 31;
        qs[n * 33 + d] = q[base + i];
        ks[n * 33 + d] = k[base + i];
        vs[n * 33 + d] = v[base + i];
    }
    __syncthreads();

    const float* rbh = rb + (size_t)head * NTOK * NTOK;
    for (int idx = tid; idx < NTOK * NTOK; idx += 128) {
        int n = idx / NTOK, m = idx - n * NTOK;
        float acc = 0.0f;
        #pragma unroll
        for (int d = 0; d < HD; d++)
            acc = fmaf(qs[n * 33 + d], ks[m * 33 + d], acc);
        S[idx] = acc * SCALE_F + rbh[idx];
    }
    __syncthreads();

    if (tid < NTOK) {
        float mx = -1e30f;
        #pragma unroll 7
        for (int m = 0; m < NTOK; m++) mx = fmaxf(mx, S[tid * NTOK + m]);
        float sum = 0.0f;
        #pragma unroll 7
        for (int m = 0; m < NTOK; m++) {
            float e = __expf(S[tid * NTOK + m] - mx);
            S[tid * NTOK + m] = e;
            sum += e;
        }
        float r = 1.0f / sum;
        #pragma unroll 7
        for (int m = 0; m < NTOK; m++) S[tid * NTOK + m] *= r;
    }
    __syncthreads();

    int bb = g >> 6;
    int wi = g & 63;
    int hr0 = (wi >> 3) * WS, wc0 = (wi & 7) * WS;
    for (int idx = tid; idx < NTOK * HD; idx += 128) {
        int n = idx >> 5, d = idx & 31;
        float acc = 0.0f;
        #pragma unroll 7
        for (int m = 0; m < NTOK; m++)
            acc = fmaf(S[n * NTOK + m], vs[m * 33 + d], acc);
        int hr = hr0 + n / WS, wc = wc0 + n % WS;
        size_t t = (size_t)bb * 3136 + (size_t)hr * 56 + wc;
        out[t * C_DIM + head * HD + d] = acc;
    }
}

// ---------------- launch ----------------
extern "C" void kernel_launch(void* const* d_in, const int* in_sizes, int n_in,
                              void* d_out, int out_size)
{
    const float* x    = (const float*)d_in[0];
    const float* Wq   = (const float*)d_in[1];
    const float* bq   = (const float*)d_in[2];
    const float* Wk   = (const float*)d_in[3];
    const float* bk   = (const float*)d_in[4];
    const float* Wv   = (const float*)d_in[5];
    const float* bv   = (const float*)d_in[6];
    const float* Wp   = (const float*)d_in[7];
    const float* bp   = (const float*)d_in[8];
    const float* rbias= (const float*)d_in[9];
    const float* g1   = (const float*)d_in[10];
    const float* b1   = (const float*)d_in[11];
    const float* g2   = (const float*)d_in[12];
    const float* b2   = (const float*)d_in[13];
    const float* W1   = (const float*)d_in[14];
    const float* bfc1 = (const float*)d_in[15];
    const float* W2   = (const float*)d_in[16];
    const float* bfc2 = (const float*)d_in[17];
    float* out = (float*)d_out;

    float *h, *q, *k, *v, *attn, *act;
    cudaGetSymbolAddress((void**)&h,    g_h);
    cudaGetSymbolAddress((void**)&q,    g_q);
    cudaGetSymbolAddress((void**)&k,    g_k);
    cudaGetSymbolAddress((void**)&v,    g_v);
    cudaGetSymbolAddress((void**)&attn, g_attn);
    cudaGetSymbolAddress((void**)&act,  g_act);

    dim3 gemm512(4, M_TOK / BM);
    dim3 gemm2048(16, M_TOK / BM);
    dim3 attn_grid(NH, B_SZ * NWIN);

    ln_kernel<<<M_TOK, 128>>>(x, g1, b1, h);
    tgemm_kernel<MODE_QKV><<<gemm512, 256>>>(h, Wq, bq, nullptr, q, C_DIM, C_DIM);
    tgemm_kernel<MODE_QKV><<<gemm512, 256>>>(h, Wk, bk, nullptr, k, C_DIM, C_DIM);
    tgemm_kernel<MODE_QKV><<<gemm512, 256>>>(h, Wv, bv, nullptr, v, C_DIM, C_DIM);
    attn_kernel<<<attn_grid, 128>>>(q, k, v, rbias, attn);
    tgemm_kernel<MODE_PROJ><<<gemm512, 256>>>(attn, Wp, bp, x, out, C_DIM, C_DIM);
    ln_kernel<<<M_TOK, 128>>>(out, g2, b2, h);
    tgemm_kernel<MODE_FC1><<<gemm2048, 256>>>(h, W1, bfc1, nullptr, act, C_DIM, HID);
    tgemm_kernel<MODE_FC2><<<gemm512, 256>>>(act, W2, bfc2, out, out, HID, C_DIM);
}